// round 12
// baseline (speedup 1.0000x reference)
#include <cuda_runtime.h>
#include <cstdint>

// LmulLinear: out[m,p] = sum_k bitcast_f32(bits(x[m,k]) + bits(w[p,k]) - OFFSET) + bias[p]
// M=256, K=512, P=512.
//
// R12: single kernel, 128 CTAs x 1024 thr = 8 k-groups x 128 thr (8 warps/SMSP,
//      2x the latency hiding of R11). BM=BN=32, 2x4 microtile, smem tree-reduce.

#define M_DIM 256
#define K_DIM 512
#define P_DIM 512
#define BM 32
#define BN 32
#define GROUPS 8
#define KG (K_DIM / GROUPS)        // 64 k per group
#define TPG 128                    // threads per group
#define SROW (KG + 4)              // 68 words; conflict-free LDS.128
#define TILE_WORDS (BM * SROW)     // 2176 words per tile
#define GROUP_WORDS (2 * TILE_WORDS)
#define SMEM_BYTES (GROUPS * GROUP_WORDS * 4)   // 139264 B

static __device__ __forceinline__ float u2f(uint32_t u) { return __uint_as_float(u); }

extern __shared__ uint32_t smem[];

__global__ void __launch_bounds__(1024, 1)
lmul_linear_kernel(const float* __restrict__ x,
                   const float* __restrict__ w,
                   const float* __restrict__ bias,
                   float* __restrict__ out)
{
    constexpr uint32_t OFFSET = 1064828928u;  // 0x3F780000

    const int tid = threadIdx.x;
    const int g   = tid >> 7;        // k-group 0..7
    const int lt  = tid & 127;       // lane in group
    const int tx  = lt & 7;          // p cols: tx + 8c, c<4
    const int ty  = lt >> 3;         // m rows: ty, ty+16
    const int m0  = blockIdx.y * BM;
    const int p0  = blockIdx.x * BN;
    const int kbase = g * KG;

    uint32_t* As = smem + g * GROUP_WORDS;   // [BM][SROW]
    uint32_t* Bs = As + TILE_WORDS;          // [BN][SROW], offset-folded

    const uint32_t* __restrict__ xu = reinterpret_cast<const uint32_t*>(x);
    const uint32_t* __restrict__ wu = reinterpret_cast<const uint32_t*>(w);

    // ---- load this group's tiles: 32 rows x 16 uint4 each; 4 uint4/thread/tile ----
    #pragma unroll
    for (int i = 0; i < 4; i++) {
        int idx  = lt + i * TPG;        // 0..511
        int row  = idx >> 4;            // 16 uint4 per row
        int col4 = idx & 15;
        uint4 va = *reinterpret_cast<const uint4*>(&xu[(m0 + row) * K_DIM + kbase + col4 * 4]);
        *reinterpret_cast<uint4*>(&As[row * SROW + col4 * 4]) = va;
        uint4 vb = *reinterpret_cast<const uint4*>(&wu[(p0 + row) * K_DIM + kbase + col4 * 4]);
        vb.x -= OFFSET; vb.y -= OFFSET; vb.z -= OFFSET; vb.w -= OFFSET;
        *reinterpret_cast<uint4*>(&Bs[row * SROW + col4 * 4]) = vb;
    }
    __syncthreads();

    // ---- main loop: 2x4 microtile, rows {ty, ty+16}, cols {tx+8c} ----
    const uint32_t* a0p = As + ty * SROW;
    const uint32_t* a1p = As + (ty + 16) * SROW;
    const uint32_t* bp  = Bs + tx * SROW;

    float acc[2][4];
    #pragma unroll
    for (int r = 0; r < 2; r++)
        #pragma unroll
        for (int c = 0; c < 4; c++) acc[r][c] = 0.f;

    #pragma unroll 4
    for (int j = 0; j < KG / 4; j++) {
        uint4 a0 = *reinterpret_cast<const uint4*>(a0p + 4 * j);
        uint4 a1 = *reinterpret_cast<const uint4*>(a1p + 4 * j);
        uint4 b[4];
        #pragma unroll
        for (int c = 0; c < 4; c++)
            b[c] = *reinterpret_cast<const uint4*>(bp + (8 * c) * SROW + 4 * j);

        #pragma unroll
        for (int c = 0; c < 4; c++) {
            acc[0][c] += u2f(a0.x + b[c].x);
            acc[1][c] += u2f(a1.x + b[c].x);
            acc[0][c] += u2f(a0.y + b[c].y);
            acc[1][c] += u2f(a1.y + b[c].y);
            acc[0][c] += u2f(a0.z + b[c].z);
            acc[1][c] += u2f(a1.z + b[c].z);
            acc[0][c] += u2f(a0.w + b[c].w);
            acc[1][c] += u2f(a1.w + b[c].w);
        }
    }

    // ---- tree reduction across 8 k-groups in smem (reuse tile space) ----
    float* Red = reinterpret_cast<float*>(smem);   // [7][128][8] floats = 28 KB

    __syncthreads();   // all tiles fully consumed
    if (g > 0) {
        float* rr = Red + ((g - 1) * TPG + lt) * 8;
        #pragma unroll
        for (int r = 0; r < 2; r++)
            #pragma unroll
            for (int c = 0; c < 4; c++) rr[r * 4 + c] = acc[r][c];
    }
    __syncthreads();

    if (g == 0) {
        #pragma unroll
        for (int gg = 0; gg < 7; gg++) {
            const float* rr = Red + (gg * TPG + lt) * 8;
            #pragma unroll
            for (int r = 0; r < 2; r++)
                #pragma unroll
                for (int c = 0; c < 4; c++) acc[r][c] += rr[r * 4 + c];
        }

        #pragma unroll
        for (int c = 0; c < 4; c++) {
            const float bv = bias[p0 + tx + 8 * c];
            acc[0][c] += bv;
            acc[1][c] += bv;
        }

        #pragma unroll
        for (int r = 0; r < 2; r++) {
            const int m = m0 + ty + 16 * r;
            float* orow = out + m * P_DIM + p0;
            #pragma unroll
            for (int c = 0; c < 4; c++)
                orow[tx + 8 * c] = acc[r][c];
        }
    }
}

extern "C" void kernel_launch(void* const* d_in, const int* in_sizes, int n_in,
                              void* d_out, int out_size)
{
    const float* x    = (const float*)d_in[0];   // (256, 512)
    const float* w    = (const float*)d_in[1];   // (512, 512)
    const float* bias = (const float*)d_in[2];   // (512,)
    float* out = (float*)d_out;                  // (256, 512)

    cudaFuncSetAttribute(lmul_linear_kernel,
                         cudaFuncAttributeMaxDynamicSharedMemorySize, SMEM_BYTES);

    dim3 grid(P_DIM / BN, M_DIM / BM);   // (16, 8) = 128 CTAs
    lmul_linear_kernel<<<grid, 1024, SMEM_BYTES>>>(x, w, bias, out);
}